// round 16
// baseline (speedup 1.0000x reference)
#include <cuda_runtime.h>
#include <cuda_fp16.h>
#include <cstdint>
#include <stdint.h>

#define BB    32
#define NN    96
#define DD    64
#define LL    5
#define NPAIR 9216            // N*N
#define PTOT  294912          // B*N*N
#define BEP   24576           // B*EP
#define EV    5
#define MAXPAIRS 49152

// ---- scratch (device globals; no allocation allowed) ----
__device__ __align__(16) float  g_T0 [PTOT*DD];
__device__ __align__(16) float  g_T1 [PTOT*DD];
__device__ __align__(16) __half g_h1 [PTOT*DD];   // h1[b,u,w,d] fp16 pair-major
__device__ __align__(16) float  g_h2 [PTOT*DD];   // h2[b,w,v,d] fp32 (edge slots)
__device__ __align__(16) __half g_M16[PTOT*DD];   // aggregation output fp16
__device__ int   g_aux[PTOT];
__device__ int   g_deg[BB*NN];
__device__ int   g_nbr[BB*NN*NN];
__device__ int   g_pairs[MAXPAIRS];
__device__ int   g_npairs;
__device__ float g_sumL[LL*BB*DD];
__device__ float g_sqL [LL*BB*DD];
__device__ float g_pool[BB*DD];

// k1h1 dyn smem: sA 128x72 fp16 [0:18432) reused as fp16 OUT tile
//                | sB 64x72 fp16 [18432:27648) | bias [27648:27904)
//                | sc [27904:28160) | sh [28160:28416)
#define SMEM_K1H1 28416
// k3 dyn smem (unchanged from R15 layout)
#define SMEM_MMA  45312

__device__ __forceinline__ uint32_t smem_u32(const void* p) {
    uint32_t a;
    asm("{ .reg .u64 t; cvta.to.shared.u64 t, %1; cvt.u32.u64 %0, t; }"
        : "=r"(a) : "l"(p));
    return a;
}
__device__ __forceinline__ void ldmA(uint32_t a[4], uint32_t addr) {
    asm volatile("ldmatrix.sync.aligned.m8n8.x4.shared.b16 {%0,%1,%2,%3}, [%4];"
        : "=r"(a[0]), "=r"(a[1]), "=r"(a[2]), "=r"(a[3]) : "r"(addr));
}
__device__ __forceinline__ void ldmB(uint32_t b[2], uint32_t addr) {
    asm volatile("ldmatrix.sync.aligned.m8n8.x2.trans.shared.b16 {%0,%1}, [%2];"
        : "=r"(b[0]), "=r"(b[1]) : "r"(addr));
}
__device__ __forceinline__ void mma16816(float c[4], const uint32_t a[4],
                                         const uint32_t b[2]) {
    asm volatile(
        "mma.sync.aligned.m16n8k16.row.col.f32.f16.f16.f32 "
        "{%0,%1,%2,%3}, {%4,%5,%6,%7}, {%8,%9}, {%0,%1,%2,%3};"
        : "+f"(c[0]), "+f"(c[1]), "+f"(c[2]), "+f"(c[3])
        : "r"(a[0]), "r"(a[1]), "r"(a[2]), "r"(a[3]), "r"(b[0]), "r"(b[1]));
}

// scale/shift from raw sums — identical formula everywhere (deterministic)
__device__ __forceinline__ void norm_coef(float su, float sq, float gm, float bt,
                                          float& sc, float& sh) {
    float mu  = su * (1.0f / NPAIR);
    float var = sq * (1.0f / NPAIR) - mu*mu;
    sc = gm * rsqrtf(var + 1e-5f);
    sh = bt - mu * sc;
}

// ---------------------------------------------------------------------------
__global__ void k_scatter(const int* __restrict__ ei, const int* __restrict__ ea) {
    int e = blockIdx.x * 256 + threadIdx.x;
    if (e >= BEP) return;
    int a = ei[e];
    int bnode = ei[BEP + e];
    int g = a / NN, u = a % NN, v = bnode % NN;
    int lab = ea[e] & 7;
    atomicMax(&g_aux[g*NPAIR + u*NN + v], (e << 3) | lab);
    atomicMax(&g_aux[g*NPAIR + v*NN + u], ((e + BEP) << 3) | lab);
}

__global__ void k_decode() {
    int i = blockIdx.x * 256 + threadIdx.x;
    if (i >= PTOT) return;
    int av = g_aux[i];
    if (av >= 0) {
        int b = i / NPAIR, r = i % NPAIR;
        int w = r / NN, v = r % NN;
        int slot = atomicAdd(&g_deg[b*NN + v], 1);
        g_nbr[(b*NN + v)*NN + slot] = w;
        int ps = atomicAdd(&g_npairs, 1);
        g_pairs[ps] = i;
    }
}

__global__ void k_initW(const int* __restrict__ x,
                        const float* __restrict__ nemb,
                        const float* __restrict__ eemb) {
    long q = (long)blockIdx.x * 256 + threadIdx.x;
    int p  = (int)(q >> 4);
    int d0 = ((int)q & 15) << 2;
    int b = p / NPAIR, r = p % NPAIR, u = r / NN, v = r % NN;
    int xu = x[b*NN + u], xv = x[b*NN + v];
    int av = g_aux[p];
    int a  = (av < 0) ? EV : (av & 7);
    float4 hu = *(const float4*)(nemb + xu*DD + d0);
    float4 hv = *(const float4*)(nemb + xv*DD + d0);
    float4 he = *(const float4*)(eemb + a*DD + d0);
    float4 o;
    o.x = hu.x + hv.x + he.x;
    o.y = hu.y + hv.y + he.y;
    o.z = hu.z + hv.z + he.z;
    o.w = hu.w + hv.w + he.w;
    *(float4*)(g_T1 + (long)p*DD + d0) = o;
}

// ---------------------------------------------------------------------------
// k1h1: h1 = relu(relu_norm(T)@W1+b1), HMMA. Bias+relu applied in fragments;
// fp16 result staged back into the A-tile smem region; one coalesced copy out.
__global__ void __launch_bounds__(256) k1h1(const float* __restrict__ Tprev,
                                            const float* __restrict__ W1,
                                            const float* __restrict__ b1,
                                            int useNorm,
                                            const float* __restrict__ pSum,
                                            const float* __restrict__ pSq,
                                            const float* __restrict__ pGam,
                                            const float* __restrict__ pBet) {
    extern __shared__ char smem[];
    __half* sA   = (__half*)smem;
    __half* sB   = (__half*)(smem + 18432);
    float* sBias = (float*)(smem + 27648);
    float* sSc   = (float*)(smem + 27904);
    float* sSh   = (float*)(smem + 28160);
    int t = threadIdx.x, w = t >> 5, l = t & 31;
    int b = blockIdx.x / 72;
    long tile0 = (long)blockIdx.x * 128;

    for (int i = t; i < 4096; i += 256) {
        int k = i >> 6, n = i & 63;
        sB[k*72 + n] = __float2half(W1[i]);
    }
    if (t < 64) {
        sBias[t] = b1[t];
        float sc = 1.f, sh = 0.f;
        if (useNorm)
            norm_coef(pSum[b*64 + t], pSq[b*64 + t], pGam[t], pBet[t], sc, sh);
        sSc[t] = sc; sSh[t] = sh;
    }
    __syncthreads();
    {
        int r = t >> 1, c0 = (t & 1) * 32;
        const float* src = Tprev + (tile0 + r) * 64 + c0;
        __half h[32];
#pragma unroll
        for (int j = 0; j < 32; j += 4) {
            float4 f = *(const float4*)(src + j);
            if (useNorm) {
                f.x = fmaxf(fmaf(f.x, sSc[c0+j+0], sSh[c0+j+0]), 0.f);
                f.y = fmaxf(fmaf(f.y, sSc[c0+j+1], sSh[c0+j+1]), 0.f);
                f.z = fmaxf(fmaf(f.z, sSc[c0+j+2], sSh[c0+j+2]), 0.f);
                f.w = fmaxf(fmaf(f.w, sSc[c0+j+3], sSh[c0+j+3]), 0.f);
            }
            h[j+0] = __float2half(f.x);
            h[j+1] = __float2half(f.y);
            h[j+2] = __float2half(f.z);
            h[j+3] = __float2half(f.w);
        }
        uint4* dst = (uint4*)(sA + r*72 + c0);
#pragma unroll
        for (int j = 0; j < 4; j++) dst[j] = ((uint4*)h)[j];
    }
    __syncthreads();

    uint32_t sAu = smem_u32(sA);
    uint32_t sBu = smem_u32(sB);
    int r0 = w * 16;
    uint32_t aF[4][4];
#pragma unroll
    for (int kk = 0; kk < 4; kk++)
        ldmA(aF[kk], sAu + (uint32_t)(((r0 + (l & 15))*72 + kk*16 + 8*(l >> 4)) << 1));

    float acc[8][4];
#pragma unroll
    for (int j = 0; j < 8; j++)
#pragma unroll
        for (int q = 0; q < 4; q++) acc[j][q] = 0.f;
#pragma unroll
    for (int j = 0; j < 8; j++) {
#pragma unroll
        for (int kk = 0; kk < 4; kk++) {
            uint32_t bF[2];
            ldmB(bF, sBu + (uint32_t)(((kk*16 + (l & 15))*72 + j*8) << 1));
            mma16816(acc[j], aF[kk], bF);
        }
    }
    __syncthreads();   // all ldmA/ldmB done -> safe to overwrite sA

    // bias + relu in fragments, fp16 into sA
    {
        int colb = 2*(l & 3);
        int row = r0 + (l >> 2);
#pragma unroll
        for (int j = 0; j < 8; j++) {
            int col = j*8 + colb;
            float b0 = sBias[col], b1v = sBias[col+1];
            __half2 h0 = __floats2half2_rn(fmaxf(acc[j][0] + b0,  0.f),
                                           fmaxf(acc[j][1] + b1v, 0.f));
            __half2 h1v = __floats2half2_rn(fmaxf(acc[j][2] + b0,  0.f),
                                            fmaxf(acc[j][3] + b1v, 0.f));
            *(uint32_t*)(sA + row*72 + col)       = *(uint32_t*)&h0;
            *(uint32_t*)(sA + (row + 8)*72 + col) = *(uint32_t*)&h1v;
        }
    }
    __syncthreads();
    // coalesced copy out: thread t -> row t>>1, 32 halfs
    {
        int row = t >> 1, c0 = (t & 1) * 32;
        const uint4* srcs = (const uint4*)(sA + row*72 + c0);
        uint4* dstg = (uint4*)(g_h1 + (tile0 + row)*64 + c0);
#pragma unroll
        for (int j = 0; j < 4; j++) dstg[j] = srcs[j];
    }
}

// ---------------------------------------------------------------------------
// k1h2: gathered GEMM over edge rows (fp32 math), fp32 output. Static smem.
__global__ void __launch_bounds__(256) k1h2(const float* __restrict__ Tprev,
                                            const float* __restrict__ Wt,
                                            const float* __restrict__ bt,
                                            int useNorm,
                                            const float* __restrict__ pSum,
                                            const float* __restrict__ pSq,
                                            const float* __restrict__ pGam,
                                            const float* __restrict__ pBet) {
    __shared__ float sIn[64][68];
    __shared__ float sW[64][64];
    __shared__ float sB[64];
    __shared__ int sP[64];
    int t = threadIdx.x;
    int np = g_npairs;
    for (int i = t; i < 4096; i += 256) sW[i >> 6][i & 63] = Wt[i];
    if (t < 64) {
        sB[t] = bt[t];
        int r = blockIdx.x * 64 + t;
        sP[t] = (r < np) ? g_pairs[r] : -1;
    }
    __syncthreads();
    for (int i = t; i < 1024; i += 256) {
        int r = i >> 4, j = (i & 15) << 2;
        int p = sP[r];
        float4 v = make_float4(0.f, 0.f, 0.f, 0.f);
        if (p >= 0) {
            v = *(const float4*)(Tprev + (long)p*64 + j);
            if (useNorm) {
                int bb = p / NPAIR;
                float4 su = *(const float4*)(pSum + bb*64 + j);
                float4 sq = *(const float4*)(pSq  + bb*64 + j);
                float4 gm = *(const float4*)(pGam + j);
                float4 bt4 = *(const float4*)(pBet + j);
                float sc, sh;
                norm_coef(su.x, sq.x, gm.x, bt4.x, sc, sh);
                v.x = fmaxf(fmaf(v.x, sc, sh), 0.0f);
                norm_coef(su.y, sq.y, gm.y, bt4.y, sc, sh);
                v.y = fmaxf(fmaf(v.y, sc, sh), 0.0f);
                norm_coef(su.z, sq.z, gm.z, bt4.z, sc, sh);
                v.z = fmaxf(fmaf(v.z, sc, sh), 0.0f);
                norm_coef(su.w, sq.w, gm.w, bt4.w, sc, sh);
                v.w = fmaxf(fmaf(v.w, sc, sh), 0.0f);
            }
        }
        sIn[r][j] = v.x; sIn[r][j+1] = v.y;
        sIn[r][j+2] = v.z; sIn[r][j+3] = v.w;
    }
    __syncthreads();

    int cg = (t & 15) * 4, rg = (t >> 4) * 4;
    float acc[4][4];
#pragma unroll
    for (int i = 0; i < 4; i++)
#pragma unroll
        for (int j = 0; j < 4; j++) acc[i][j] = 0.0f;
#pragma unroll 16
    for (int k = 0; k < 64; k++) {
        float4 wv = *(float4*)&sW[k][cg];
#pragma unroll
        for (int i = 0; i < 4; i++) {
            float a = sIn[rg + i][k];
            acc[i][0] = fmaf(a, wv.x, acc[i][0]);
            acc[i][1] = fmaf(a, wv.y, acc[i][1]);
            acc[i][2] = fmaf(a, wv.z, acc[i][2]);
            acc[i][3] = fmaf(a, wv.w, acc[i][3]);
        }
    }
    float4 bb = *(float4*)&sB[cg];
#pragma unroll
    for (int i = 0; i < 4; i++) {
        int p = sP[rg + i];
        if (p >= 0) {
            float4 o;
            o.x = fmaxf(acc[i][0] + bb.x, 0.0f);
            o.y = fmaxf(acc[i][1] + bb.y, 0.0f);
            o.z = fmaxf(acc[i][2] + bb.z, 0.0f);
            o.w = fmaxf(acc[i][3] + bb.w, 0.0f);
            *(float4*)(g_h2 + (long)p*64 + cg) = o;
        }
    }
}

// ---------------------------------------------------------------------------
// K2 sparse: M16[b,u,v,d] = sum_{w in N(v)} h1[b,u,w,d]*h2[b,w,v,d] (fp16 out)
__global__ void __launch_bounds__(256) k2_sparse() {
    __shared__ int snbr[96];
    __shared__ float sh2[96*64];
    int t = threadIdx.x;
    int b = blockIdx.x / NN, v = blockIdx.x % NN;
    int deg = g_deg[b*NN + v];
    if (t < 96) snbr[t] = (t < deg) ? g_nbr[(b*NN + v)*NN + t] : 0;
    __syncthreads();
    for (int q = t; q < deg*16; q += 256) {
        int s = q >> 4, j = (q & 15) << 2;
        int w = snbr[s];
        *(float4*)&sh2[s*64 + j] =
            *(const float4*)(g_h2 + ((long)(b*NPAIR + w*NN + v) << 6) + j);
    }
    __syncthreads();

    int d0 = (t & 7) * 8, ug = t >> 3;      // each ug owns 3 u's
    float acc[3][8];
#pragma unroll
    for (int i = 0; i < 3; i++)
#pragma unroll
        for (int j = 0; j < 8; j++) acc[i][j] = 0.f;

    const __half* h1b = g_h1 + ((long)b*NPAIR)*64 + (long)(ug*3)*6144 + d0;
    for (int s = 0; s < deg; s++) {
        int w = snbr[s];
        float4 g0 = *(float4*)&sh2[s*64 + d0];
        float4 g1 = *(float4*)&sh2[s*64 + d0 + 4];
        const __half* p0 = h1b + (long)w*64;
#pragma unroll
        for (int i = 0; i < 3; i++) {
            uint4 au = *(const uint4*)(p0 + (long)i*6144);
            __half2* hp = (__half2*)&au;
            float2 a0 = __half22float2(hp[0]);
            float2 a1 = __half22float2(hp[1]);
            float2 a2 = __half22float2(hp[2]);
            float2 a3 = __half22float2(hp[3]);
            acc[i][0] = fmaf(a0.x, g0.x, acc[i][0]);
            acc[i][1] = fmaf(a0.y, g0.y, acc[i][1]);
            acc[i][2] = fmaf(a1.x, g0.z, acc[i][2]);
            acc[i][3] = fmaf(a1.y, g0.w, acc[i][3]);
            acc[i][4] = fmaf(a2.x, g1.x, acc[i][4]);
            acc[i][5] = fmaf(a2.y, g1.y, acc[i][5]);
            acc[i][6] = fmaf(a3.x, g1.z, acc[i][6]);
            acc[i][7] = fmaf(a3.y, g1.w, acc[i][7]);
        }
    }
    __half* Mb = g_M16 + ((long)(b*NPAIR + v))*64 + (long)(ug*3)*6144 + d0;
#pragma unroll
    for (int i = 0; i < 3; i++) {
        __half hh[8];
#pragma unroll
        for (int j = 0; j < 8; j++) hh[j] = __float2half_rn(acc[i][j]);
        *(uint4*)(Mb + (long)i*6144) = *(uint4*)hh;
    }
}

// ---------------------------------------------------------------------------
// k3_mma: Tcur = relu_norm(Tprev) + M16@Wm + bm, HMMA; accumulates raw stats.
__global__ void __launch_bounds__(256) k3_mma(const float* __restrict__ Tprev,
                                              const float* __restrict__ Wm,
                                              const float* __restrict__ bm,
                                              int useNorm,
                                              float* __restrict__ Tcur,
                                              const float* __restrict__ pSum,
                                              const float* __restrict__ pSq,
                                              const float* __restrict__ pGam,
                                              const float* __restrict__ pBet,
                                              float* __restrict__ oSum,
                                              float* __restrict__ oSq) {
    extern __shared__ char smem[];
    __half* sA   = (__half*)smem;
    float*  sO   = (float*)smem;
    __half* sB   = (__half*)(smem + 34816);
    float* sBm   = (float*)(smem + 44032);
    float* sSc   = (float*)(smem + 44288);
    float* sSh   = (float*)(smem + 44544);
    float* sSum  = (float*)(smem + 44800);
    float* sSq   = (float*)(smem + 45056);
    int t = threadIdx.x, w = t >> 5, l = t & 31;
    int b = blockIdx.x / 72;
    long tile0 = (long)blockIdx.x * 128;

    for (int i = t; i < 4096; i += 256) {
        int k = i >> 6, n = i & 63;
        sB[k*72 + n] = __float2half(Wm[i]);
    }
    if (t < 64) {
        sBm[t] = bm[t];
        float sc = 1.f, sh = 0.f;
        if (useNorm)
            norm_coef(pSum[b*64 + t], pSq[b*64 + t], pGam[t], pBet[t], sc, sh);
        sSc[t] = sc; sSh[t] = sh;
        sSum[t] = 0.f;
        sSq[t] = 0.f;
    }
    {
        int r = t >> 1, c0 = (t & 1) * 32;
        const uint4* src = (const uint4*)(g_M16 + (tile0 + r)*64 + c0);
        uint4* dst = (uint4*)(sA + r*72 + c0);
#pragma unroll
        for (int j = 0; j < 4; j++) dst[j] = src[j];
    }
    __syncthreads();

    uint32_t sAu = smem_u32(sA);
    uint32_t sBu = smem_u32(sB);
    int r0 = w * 16;
    uint32_t aF[4][4];
#pragma unroll
    for (int kk = 0; kk < 4; kk++)
        ldmA(aF[kk], sAu + (uint32_t)(((r0 + (l & 15))*72 + kk*16 + 8*(l >> 4)) << 1));

    float acc[8][4];
#pragma unroll
    for (int j = 0; j < 8; j++)
#pragma unroll
        for (int q = 0; q < 4; q++) acc[j][q] = 0.f;

#pragma unroll
    for (int j = 0; j < 8; j++) {
#pragma unroll
        for (int kk = 0; kk < 4; kk++) {
            uint32_t bF[2];
            ldmB(bF, sBu + (uint32_t)(((kk*16 + (l & 15))*72 + j*8) << 1));
            mma16816(acc[j], aF[kk], bF);
        }
    }
    __syncthreads();
#pragma unroll
    for (int j = 0; j < 8; j++) {
        int row = r0 + (l >> 2);
        int col = j*8 + 2*(l & 3);
        *(float2*)&sO[row*68 + col]     = make_float2(acc[j][0], acc[j][1]);
        *(float2*)&sO[(row+8)*68 + col] = make_float2(acc[j][2], acc[j][3]);
    }
    __syncthreads();
    {
        int c2 = (t & 31) * 2, grp = t >> 5;
        float b0 = sBm[c2], b1 = sBm[c2+1];
        float sc0 = sSc[c2], sc1 = sSc[c2+1];
        float sh0 = sSh[c2], sh1 = sSh[c2+1];
        float cs0 = 0.f, cs1 = 0.f, cq0 = 0.f, cq1 = 0.f;
#pragma unroll
        for (int i = 0; i < 16; i++) {
            int r = grp*16 + i;
            long p = tile0 + r;
            float2 m = *(float2*)&sO[r*68 + c2];
            float2 tv = *(const float2*)(Tprev + p*64 + c2);
            if (useNorm) {
                tv.x = fmaxf(fmaf(tv.x, sc0, sh0), 0.f);
                tv.y = fmaxf(fmaf(tv.y, sc1, sh1), 0.f);
            }
            float o0 = m.x + b0 + tv.x;
            float o1 = m.y + b1 + tv.y;
            *(float2*)(Tcur + p*64 + c2) = make_float2(o0, o1);
            cs0 += o0; cq0 += o0*o0;
            cs1 += o1; cq1 += o1*o1;
        }
        atomicAdd(&sSum[c2],   cs0);
        atomicAdd(&sSum[c2+1], cs1);
        atomicAdd(&sSq[c2],    cq0);
        atomicAdd(&sSq[c2+1],  cq1);
    }
    __syncthreads();
    if (t < 64) {
        atomicAdd(&oSum[b*64 + t], sSum[t]);
        atomicAdd(&oSq [b*64 + t], sSq[t]);
    }
}

// k_pool: normalized relu pooled sums; norm coefs computed inline per block.
__global__ void __launch_bounds__(256) k_pool(const float* __restrict__ T,
                                              const float* __restrict__ pSum,
                                              const float* __restrict__ pSq,
                                              const float* __restrict__ pGam,
                                              const float* __restrict__ pBet) {
    __shared__ float sp[64];
    __shared__ float sScP[64], sShP[64];
    int t = threadIdx.x;
    int b = blockIdx.x / 576;
    if (t < 64) {
        float sc, sh;
        norm_coef(pSum[b*64 + t], pSq[b*64 + t], pGam[t], pBet[t], sc, sh);
        sScP[t] = sc; sShP[t] = sh;
        sp[t] = 0.0f;
    }
    __syncthreads();
    long q = (long)blockIdx.x * 256 + t;
    long idx = q * 4;
    int d0 = (int)(idx & 63);
    float4 v  = *(const float4*)(T + idx);
    float4 sc = *(const float4*)&sScP[d0];
    float4 sh = *(const float4*)&sShP[d0];
    float4 o;
    o.x = fmaxf(fmaf(v.x, sc.x, sh.x), 0.0f);
    o.y = fmaxf(fmaf(v.y, sc.y, sh.y), 0.0f);
    o.z = fmaxf(fmaf(v.z, sc.z, sh.z), 0.0f);
    o.w = fmaxf(fmaf(v.w, sc.w, sh.w), 0.0f);
    atomicAdd(&sp[d0+0], o.x);
    atomicAdd(&sp[d0+1], o.y);
    atomicAdd(&sp[d0+2], o.z);
    atomicAdd(&sp[d0+3], o.w);
    __syncthreads();
    if (t < 64) atomicAdd(&g_pool[b*64 + t], sp[t]);
}

__global__ void k5_out(const float* __restrict__ pw,
                       const float* __restrict__ pb,
                       float* __restrict__ out) {
    int t = threadIdx.x;
    int b = t >> 5, lane = t & 31;
    float v = g_pool[b*64 + lane]      * pw[lane]
            + g_pool[b*64 + lane + 32] * pw[lane + 32];
#pragma unroll
    for (int o = 16; o > 0; o >>= 1) v += __shfl_down_sync(0xffffffffu, v, o);
    if (lane == 0) out[b] = v + pb[0];
}

// ---------------------------------------------------------------------------
extern "C" void kernel_launch(void* const* d_in, const int* in_sizes, int n_in,
                              void* d_out, int out_size) {
    (void)in_sizes; (void)n_in; (void)out_size;
    const int*   x    = (const int*)d_in[0];
    const int*   ei   = (const int*)d_in[1];
    const int*   ea   = (const int*)d_in[2];
    const float* nemb = (const float*)d_in[3];
    const float* eemb = (const float*)d_in[4];
    const float* W1   = (const float*)d_in[5];
    const float* b1   = (const float*)d_in[6];
    const float* W2   = (const float*)d_in[7];
    const float* b2   = (const float*)d_in[8];
    const float* Wm   = (const float*)d_in[9];
    const float* bm   = (const float*)d_in[10];
    const float* gam  = (const float*)d_in[11];
    const float* bet  = (const float*)d_in[12];
    const float* pw   = (const float*)d_in[13];
    const float* pb   = (const float*)d_in[14];
    float* out = (float*)d_out;

    float* gT0;  cudaGetSymbolAddress((void**)&gT0,  g_T0);
    float* gT1;  cudaGetSymbolAddress((void**)&gT1,  g_T1);
    float* gSum; cudaGetSymbolAddress((void**)&gSum, g_sumL);
    float* gSq;  cudaGetSymbolAddress((void**)&gSq,  g_sqL);
    void* pAux;  cudaGetSymbolAddress(&pAux,  g_aux);
    void* pDeg;  cudaGetSymbolAddress(&pDeg,  g_deg);
    void* pNp;   cudaGetSymbolAddress(&pNp,   g_npairs);
    void* pPool; cudaGetSymbolAddress(&pPool, g_pool);

    cudaFuncSetAttribute(k1h1,   cudaFuncAttributeMaxDynamicSharedMemorySize, SMEM_K1H1);
    cudaFuncSetAttribute(k3_mma, cudaFuncAttributeMaxDynamicSharedMemorySize, SMEM_MMA);

    cudaMemsetAsync(pAux, 0xFF, PTOT * sizeof(int));          // g_aux = -1
    cudaMemsetAsync(pDeg, 0, BB*NN * sizeof(int));
    cudaMemsetAsync(pNp, 0, sizeof(int));
    cudaMemsetAsync(pPool, 0, BB*DD * sizeof(float));
    cudaMemsetAsync(gSum, 0, LL*BB*DD * sizeof(float));
    cudaMemsetAsync(gSq, 0, LL*BB*DD * sizeof(float));

    k_scatter<<<96, 256>>>(ei, ea);
    k_decode<<<1152, 256>>>();
    k_initW<<<18432, 256>>>(x, nemb, eemb);   // -> g_T1

    for (int l = 0; l < LL; l++) {
        float* Tprev = (l % 2 == 0) ? gT1 : gT0;
        float* Tcur  = (l % 2 == 0) ? gT0 : gT1;
        int useNorm  = (l > 0) ? 1 : 0;
        int lp = (l > 0) ? (l - 1) : 0;
        const float* pSum = gSum + lp*BB*DD;
        const float* pSq  = gSq  + lp*BB*DD;
        const float* pGam = gam + lp*64;
        const float* pBet = bet + lp*64;
        k1h1<<<2304, 256, SMEM_K1H1>>>(Tprev, W1 + l*4096, b1 + l*64, useNorm,
                                       pSum, pSq, pGam, pBet);
        k1h2<<<768, 256>>>(Tprev, W2 + l*4096, b2 + l*64, useNorm,
                           pSum, pSq, pGam, pBet);
        k2_sparse<<<3072, 256>>>();
        k3_mma<<<2304, 256, SMEM_MMA>>>(Tprev, Wm + l*4096, bm + l*64,
                                        useNorm, Tcur,
                                        pSum, pSq, pGam, pBet,
                                        gSum + l*BB*DD, gSq + l*BB*DD);
    }
    k_pool<<<18432, 256>>>(gT0,
                           gSum + (LL-1)*BB*DD, gSq + (LL-1)*BB*DD,
                           gam + (LL-1)*64, bet + (LL-1)*64);
    k5_out<<<1, 1024>>>(pw, pb, out);
}

// round 17
// speedup vs baseline: 1.0804x; 1.0804x over previous
#include <cuda_runtime.h>
#include <cuda_fp16.h>
#include <cstdint>
#include <stdint.h>

#define BB    32
#define NN    96
#define DD    64
#define LL    5
#define NPAIR 9216            // N*N
#define PTOT  294912          // B*N*N
#define BEP   24576           // B*EP
#define EV    5
#define MAXPAIRS 49152

// ---- scratch (device globals; no allocation allowed) ----
__device__ __align__(16) float  g_T0 [PTOT*DD];
__device__ __align__(16) float  g_T1 [PTOT*DD];
__device__ __align__(16) __half g_h1 [PTOT*DD];   // h1[b,u,w,d] fp16 pair-major
__device__ __align__(16) float  g_h2 [PTOT*DD];   // h2[b,w,v,d] fp32 (edge slots)
__device__ __align__(16) __half g_M16[PTOT*DD];   // aggregation output fp16
__device__ int   g_aux[PTOT];
__device__ int   g_deg[BB*NN];
__device__ int   g_nbr[BB*NN*NN];
__device__ int   g_pairs[MAXPAIRS];
__device__ int   g_npairs;
__device__ float g_sumL[LL*BB*DD];
__device__ float g_sqL [LL*BB*DD];
__device__ float g_pool[BB*DD];

// k1_fused dyn smem union:
//  h1 path: sA 128x72 fp16 [0:18432) (reused as fp16 out) | sB 64x72 fp16 [18432:27648)
//           | bias [27648:27904) | sc [27904:28160) | sh [28160:28416)
//  h2 path: sIn 64x68 f32 [0:17408) | sW 64x64 f32 [17408:33792)
//           | sB [33792:34048) | sP [34048:34304)
#define SMEM_K1  34304
// k3 dyn smem (R15 layout)
#define SMEM_MMA 45312

__device__ __forceinline__ uint32_t smem_u32(const void* p) {
    uint32_t a;
    asm("{ .reg .u64 t; cvta.to.shared.u64 t, %1; cvt.u32.u64 %0, t; }"
        : "=r"(a) : "l"(p));
    return a;
}
__device__ __forceinline__ void ldmA(uint32_t a[4], uint32_t addr) {
    asm volatile("ldmatrix.sync.aligned.m8n8.x4.shared.b16 {%0,%1,%2,%3}, [%4];"
        : "=r"(a[0]), "=r"(a[1]), "=r"(a[2]), "=r"(a[3]) : "r"(addr));
}
__device__ __forceinline__ void ldmB(uint32_t b[2], uint32_t addr) {
    asm volatile("ldmatrix.sync.aligned.m8n8.x2.trans.shared.b16 {%0,%1}, [%2];"
        : "=r"(b[0]), "=r"(b[1]) : "r"(addr));
}
__device__ __forceinline__ void mma16816(float c[4], const uint32_t a[4],
                                         const uint32_t b[2]) {
    asm volatile(
        "mma.sync.aligned.m16n8k16.row.col.f32.f16.f16.f32 "
        "{%0,%1,%2,%3}, {%4,%5,%6,%7}, {%8,%9}, {%0,%1,%2,%3};"
        : "+f"(c[0]), "+f"(c[1]), "+f"(c[2]), "+f"(c[3])
        : "r"(a[0]), "r"(a[1]), "r"(a[2]), "r"(a[3]), "r"(b[0]), "r"(b[1]));
}

// scale/shift from raw sums — identical formula everywhere (deterministic)
__device__ __forceinline__ void norm_coef(float su, float sq, float gm, float bt,
                                          float& sc, float& sh) {
    float mu  = su * (1.0f / NPAIR);
    float var = sq * (1.0f / NPAIR) - mu*mu;
    sc = gm * rsqrtf(var + 1e-5f);
    sh = bt - mu * sc;
}

// ---------------------------------------------------------------------------
__global__ void k_scatter(const int* __restrict__ ei, const int* __restrict__ ea) {
    int e = blockIdx.x * 256 + threadIdx.x;
    if (e >= BEP) return;
    int a = ei[e];
    int bnode = ei[BEP + e];
    int g = a / NN, u = a % NN, v = bnode % NN;
    int lab = ea[e] & 7;
    atomicMax(&g_aux[g*NPAIR + u*NN + v], (e << 3) | lab);
    atomicMax(&g_aux[g*NPAIR + v*NN + u], ((e + BEP) << 3) | lab);
}

__global__ void k_decode() {
    int i = blockIdx.x * 256 + threadIdx.x;
    if (i >= PTOT) return;
    int av = g_aux[i];
    if (av >= 0) {
        int b = i / NPAIR, r = i % NPAIR;
        int w = r / NN, v = r % NN;
        int slot = atomicAdd(&g_deg[b*NN + v], 1);
        g_nbr[(b*NN + v)*NN + slot] = w;
        int ps = atomicAdd(&g_npairs, 1);
        g_pairs[ps] = i;
    }
}

__global__ void k_initW(const int* __restrict__ x,
                        const float* __restrict__ nemb,
                        const float* __restrict__ eemb) {
    long q = (long)blockIdx.x * 256 + threadIdx.x;
    int p  = (int)(q >> 4);
    int d0 = ((int)q & 15) << 2;
    int b = p / NPAIR, r = p % NPAIR, u = r / NN, v = r % NN;
    int xu = x[b*NN + u], xv = x[b*NN + v];
    int av = g_aux[p];
    int a  = (av < 0) ? EV : (av & 7);
    float4 hu = *(const float4*)(nemb + xu*DD + d0);
    float4 hv = *(const float4*)(nemb + xv*DD + d0);
    float4 he = *(const float4*)(eemb + a*DD + d0);
    float4 o;
    o.x = hu.x + hv.x + he.x;
    o.y = hu.y + hv.y + he.y;
    o.z = hu.z + hv.z + he.z;
    o.w = hu.w + hv.w + he.w;
    *(float4*)(g_T1 + (long)p*DD + d0) = o;
}

// ---------------------------------------------------------------------------
// k1_fused: blocks [0,1152): h1 via HMMA, 2 tiles of 128 pairs per block,
//           fragment epilogue, fp16 staged in sA, coalesced copy-out.
//           blocks [1152,1920): h2 gathered fp32 GEMM over edge rows.
__global__ void __launch_bounds__(256) k1_fused(const float* __restrict__ Tprev,
                                                const float* __restrict__ W1,
                                                const float* __restrict__ b1,
                                                const float* __restrict__ W2,
                                                const float* __restrict__ b2,
                                                int useNorm,
                                                const float* __restrict__ pSum,
                                                const float* __restrict__ pSq,
                                                const float* __restrict__ pGam,
                                                const float* __restrict__ pBet) {
    extern __shared__ char smem[];
    int t = threadIdx.x;
    if (blockIdx.x < 1152) {
        // ---------------- h1 path (HMMA, 2 tiles) ----------------
        __half* sA   = (__half*)smem;
        __half* sB   = (__half*)(smem + 18432);
        float* sBias = (float*)(smem + 27648);
        float* sSc   = (float*)(smem + 27904);
        float* sSh   = (float*)(smem + 28160);
        int w = t >> 5, l = t & 31;
        int b = blockIdx.x / 36;                  // 36 blocks per graph

        for (int i = t; i < 4096; i += 256) {
            int k = i >> 6, n = i & 63;
            sB[k*72 + n] = __float2half(W1[i]);
        }
        if (t < 64) {
            sBias[t] = b1[t];
            float sc = 1.f, sh = 0.f;
            if (useNorm)
                norm_coef(pSum[b*64 + t], pSq[b*64 + t], pGam[t], pBet[t], sc, sh);
            sSc[t] = sc; sSh[t] = sh;
        }
        __syncthreads();

        uint32_t sAu = smem_u32(sA);
        uint32_t sBu = smem_u32(sB);
        int r0 = w * 16;

        for (int it = 0; it < 2; it++) {
            long tile0 = ((long)blockIdx.x * 2 + it) * 128;
            // stage A: fp32 -> norm -> fp16
            {
                int r = t >> 1, c0 = (t & 1) * 32;
                const float* src = Tprev + (tile0 + r) * 64 + c0;
                __half h[32];
#pragma unroll
                for (int j = 0; j < 32; j += 4) {
                    float4 f = *(const float4*)(src + j);
                    if (useNorm) {
                        f.x = fmaxf(fmaf(f.x, sSc[c0+j+0], sSh[c0+j+0]), 0.f);
                        f.y = fmaxf(fmaf(f.y, sSc[c0+j+1], sSh[c0+j+1]), 0.f);
                        f.z = fmaxf(fmaf(f.z, sSc[c0+j+2], sSh[c0+j+2]), 0.f);
                        f.w = fmaxf(fmaf(f.w, sSc[c0+j+3], sSh[c0+j+3]), 0.f);
                    }
                    h[j+0] = __float2half(f.x);
                    h[j+1] = __float2half(f.y);
                    h[j+2] = __float2half(f.z);
                    h[j+3] = __float2half(f.w);
                }
                uint4* dst = (uint4*)(sA + r*72 + c0);
#pragma unroll
                for (int j = 0; j < 4; j++) dst[j] = ((uint4*)h)[j];
            }
            __syncthreads();

            uint32_t aF[4][4];
#pragma unroll
            for (int kk = 0; kk < 4; kk++)
                ldmA(aF[kk], sAu + (uint32_t)(((r0 + (l & 15))*72 + kk*16 + 8*(l >> 4)) << 1));

            float acc[8][4];
#pragma unroll
            for (int j = 0; j < 8; j++)
#pragma unroll
                for (int q = 0; q < 4; q++) acc[j][q] = 0.f;
#pragma unroll
            for (int j = 0; j < 8; j++) {
#pragma unroll
                for (int kk = 0; kk < 4; kk++) {
                    uint32_t bF[2];
                    ldmB(bF, sBu + (uint32_t)(((kk*16 + (l & 15))*72 + j*8) << 1));
                    mma16816(acc[j], aF[kk], bF);
                }
            }
            __syncthreads();   // done reading sA

            // bias + relu in fragments, fp16 into sA
            {
                int colb = 2*(l & 3);
                int row = r0 + (l >> 2);
#pragma unroll
                for (int j = 0; j < 8; j++) {
                    int col = j*8 + colb;
                    float b0 = sBias[col], b1v = sBias[col+1];
                    __half2 h0 = __floats2half2_rn(fmaxf(acc[j][0] + b0,  0.f),
                                                   fmaxf(acc[j][1] + b1v, 0.f));
                    __half2 h1v = __floats2half2_rn(fmaxf(acc[j][2] + b0,  0.f),
                                                    fmaxf(acc[j][3] + b1v, 0.f));
                    *(uint32_t*)(sA + row*72 + col)       = *(uint32_t*)&h0;
                    *(uint32_t*)(sA + (row + 8)*72 + col) = *(uint32_t*)&h1v;
                }
            }
            __syncthreads();
            // coalesced copy out
            {
                int row = t >> 1, c0 = (t & 1) * 32;
                const uint4* srcs = (const uint4*)(sA + row*72 + c0);
                uint4* dstg = (uint4*)(g_h1 + (tile0 + row)*64 + c0);
#pragma unroll
                for (int j = 0; j < 4; j++) dstg[j] = srcs[j];
            }
            __syncthreads();   // copy-out reads done before next staging
        }
    } else {
        // ---------------- h2 path (gathered fp32) ----------------
        float* sIn = (float*)smem;                 // [64][68]
        float* sW  = (float*)(smem + 17408);       // [64][64]
        float* sB  = (float*)(smem + 33792);
        int*   sP  = (int*)(smem + 34048);
        int ebid = blockIdx.x - 1152;
        int np = g_npairs;
        for (int i = t; i < 4096; i += 256) sW[(i >> 6)*64 + (i & 63)] = W2[i];
        if (t < 64) {
            sB[t] = b2[t];
            int r = ebid * 64 + t;
            sP[t] = (r < np) ? g_pairs[r] : -1;
        }
        __syncthreads();
        for (int i = t; i < 1024; i += 256) {
            int r = i >> 4, j = (i & 15) << 2;
            int p = sP[r];
            float4 v = make_float4(0.f, 0.f, 0.f, 0.f);
            if (p >= 0) {
                v = *(const float4*)(Tprev + (long)p*64 + j);
                if (useNorm) {
                    int bb = p / NPAIR;
                    float4 su = *(const float4*)(pSum + bb*64 + j);
                    float4 sq = *(const float4*)(pSq  + bb*64 + j);
                    float4 gm = *(const float4*)(pGam + j);
                    float4 bt4 = *(const float4*)(pBet + j);
                    float sc, sh;
                    norm_coef(su.x, sq.x, gm.x, bt4.x, sc, sh);
                    v.x = fmaxf(fmaf(v.x, sc, sh), 0.0f);
                    norm_coef(su.y, sq.y, gm.y, bt4.y, sc, sh);
                    v.y = fmaxf(fmaf(v.y, sc, sh), 0.0f);
                    norm_coef(su.z, sq.z, gm.z, bt4.z, sc, sh);
                    v.z = fmaxf(fmaf(v.z, sc, sh), 0.0f);
                    norm_coef(su.w, sq.w, gm.w, bt4.w, sc, sh);
                    v.w = fmaxf(fmaf(v.w, sc, sh), 0.0f);
                }
            }
            sIn[r*68+j] = v.x; sIn[r*68+j+1] = v.y;
            sIn[r*68+j+2] = v.z; sIn[r*68+j+3] = v.w;
        }
        __syncthreads();

        int cg = (t & 15) * 4, rg = (t >> 4) * 4;
        float acc[4][4];
#pragma unroll
        for (int i = 0; i < 4; i++)
#pragma unroll
            for (int j = 0; j < 4; j++) acc[i][j] = 0.0f;
#pragma unroll 16
        for (int k = 0; k < 64; k++) {
            float4 wv = *(float4*)&sW[k*64 + cg];
#pragma unroll
            for (int i = 0; i < 4; i++) {
                float a = sIn[(rg + i)*68 + k];
                acc[i][0] = fmaf(a, wv.x, acc[i][0]);
                acc[i][1] = fmaf(a, wv.y, acc[i][1]);
                acc[i][2] = fmaf(a, wv.z, acc[i][2]);
                acc[i][3] = fmaf(a, wv.w, acc[i][3]);
            }
        }
        float4 bb = *(float4*)&sB[cg];
#pragma unroll
        for (int i = 0; i < 4; i++) {
            int p = sP[rg + i];
            if (p >= 0) {
                float4 o;
                o.x = fmaxf(acc[i][0] + bb.x, 0.0f);
                o.y = fmaxf(acc[i][1] + bb.y, 0.0f);
                o.z = fmaxf(acc[i][2] + bb.z, 0.0f);
                o.w = fmaxf(acc[i][3] + bb.w, 0.0f);
                *(float4*)(g_h2 + (long)p*64 + cg) = o;
            }
        }
    }
}

// ---------------------------------------------------------------------------
// K2 sparse: M16[b,u,v,d] = sum_{w in N(v)} h1[b,u,w,d]*h2[b,w,v,d] (fp16 out)
__global__ void __launch_bounds__(256) k2_sparse() {
    __shared__ int snbr[96];
    __shared__ float sh2[96*64];
    int t = threadIdx.x;
    int b = blockIdx.x / NN, v = blockIdx.x % NN;
    int deg = g_deg[b*NN + v];
    if (t < 96) snbr[t] = (t < deg) ? g_nbr[(b*NN + v)*NN + t] : 0;
    __syncthreads();
    for (int q = t; q < deg*16; q += 256) {
        int s = q >> 4, j = (q & 15) << 2;
        int w = snbr[s];
        *(float4*)&sh2[s*64 + j] =
            *(const float4*)(g_h2 + ((long)(b*NPAIR + w*NN + v) << 6) + j);
    }
    __syncthreads();

    int d0 = (t & 7) * 8, ug = t >> 3;      // each ug owns 3 u's
    float acc[3][8];
#pragma unroll
    for (int i = 0; i < 3; i++)
#pragma unroll
        for (int j = 0; j < 8; j++) acc[i][j] = 0.f;

    const __half* h1b = g_h1 + ((long)b*NPAIR)*64 + (long)(ug*3)*6144 + d0;
    for (int s = 0; s < deg; s++) {
        int w = snbr[s];
        float4 g0 = *(float4*)&sh2[s*64 + d0];
        float4 g1 = *(float4*)&sh2[s*64 + d0 + 4];
        const __half* p0 = h1b + (long)w*64;
#pragma unroll
        for (int i = 0; i < 3; i++) {
            uint4 au = *(const uint4*)(p0 + (long)i*6144);
            __half2* hp = (__half2*)&au;
            float2 a0 = __half22float2(hp[0]);
            float2 a1 = __half22float2(hp[1]);
            float2 a2 = __half22float2(hp[2]);
            float2 a3 = __half22float2(hp[3]);
            acc[i][0] = fmaf(a0.x, g0.x, acc[i][0]);
            acc[i][1] = fmaf(a0.y, g0.y, acc[i][1]);
            acc[i][2] = fmaf(a1.x, g0.z, acc[i][2]);
            acc[i][3] = fmaf(a1.y, g0.w, acc[i][3]);
            acc[i][4] = fmaf(a2.x, g1.x, acc[i][4]);
            acc[i][5] = fmaf(a2.y, g1.y, acc[i][5]);
            acc[i][6] = fmaf(a3.x, g1.z, acc[i][6]);
            acc[i][7] = fmaf(a3.y, g1.w, acc[i][7]);
        }
    }
    __half* Mb = g_M16 + ((long)(b*NPAIR + v))*64 + (long)(ug*3)*6144 + d0;
#pragma unroll
    for (int i = 0; i < 3; i++) {
        __half hh[8];
#pragma unroll
        for (int j = 0; j < 8; j++) hh[j] = __float2half_rn(acc[i][j]);
        *(uint4*)(Mb + (long)i*6144) = *(uint4*)hh;
    }
}

// ---------------------------------------------------------------------------
// k3_mma: Tcur = relu_norm(Tprev) + M16@Wm + bm, HMMA; accumulates raw stats.
__global__ void __launch_bounds__(256) k3_mma(const float* __restrict__ Tprev,
                                              const float* __restrict__ Wm,
                                              const float* __restrict__ bm,
                                              int useNorm,
                                              float* __restrict__ Tcur,
                                              const float* __restrict__ pSum,
                                              const float* __restrict__ pSq,
                                              const float* __restrict__ pGam,
                                              const float* __restrict__ pBet,
                                              float* __restrict__ oSum,
                                              float* __restrict__ oSq) {
    extern __shared__ char smem[];
    __half* sA   = (__half*)smem;
    float*  sO   = (float*)smem;
    __half* sB   = (__half*)(smem + 34816);
    float* sBm   = (float*)(smem + 44032);
    float* sSc   = (float*)(smem + 44288);
    float* sSh   = (float*)(smem + 44544);
    float* sSum  = (float*)(smem + 44800);
    float* sSq   = (float*)(smem + 45056);
    int t = threadIdx.x, w = t >> 5, l = t & 31;
    int b = blockIdx.x / 72;
    long tile0 = (long)blockIdx.x * 128;

    for (int i = t; i < 4096; i += 256) {
        int k = i >> 6, n = i & 63;
        sB[k*72 + n] = __float2half(Wm[i]);
    }
    if (t < 64) {
        sBm[t] = bm[t];
        float sc = 1.f, sh = 0.f;
        if (useNorm)
            norm_coef(pSum[b*64 + t], pSq[b*64 + t], pGam[t], pBet[t], sc, sh);
        sSc[t] = sc; sSh[t] = sh;
        sSum[t] = 0.f;
        sSq[t] = 0.f;
    }
    {
        int r = t >> 1, c0 = (t & 1) * 32;
        const uint4* src = (const uint4*)(g_M16 + (tile0 + r)*64 + c0);
        uint4* dst = (uint4*)(sA + r*72 + c0);
#pragma unroll
        for (int j = 0; j < 4; j++) dst[j] = src[j];
    }
    __syncthreads();

    uint32_t sAu = smem_u32(sA);
    uint32_t sBu = smem_u32(sB);
    int r0 = w * 16;
    uint32_t aF[4][4];
#pragma unroll
    for (int kk = 0; kk < 4; kk++)
        ldmA(aF[kk], sAu + (uint32_t)(((r0 + (l & 15))*72 + kk*16 + 8*(l >> 4)) << 1));

    float acc[8][4];
#pragma unroll
    for (int j = 0; j < 8; j++)
#pragma unroll
        for (int q = 0; q < 4; q++) acc[j][q] = 0.f;

#pragma unroll
    for (int j = 0; j < 8; j++) {
#pragma unroll
        for (int kk = 0; kk < 4; kk++) {
            uint32_t bF[2];
            ldmB(bF, sBu + (uint32_t)(((kk*16 + (l & 15))*72 + j*8) << 1));
            mma16816(acc[j], aF[kk], bF);
        }
    }
    __syncthreads();
#pragma unroll
    for (int j = 0; j < 8; j++) {
        int row = r0 + (l >> 2);
        int col = j*8 + 2*(l & 3);
        *(float2*)&sO[row*68 + col]     = make_float2(acc[j][0], acc[j][1]);
        *(float2*)&sO[(row+8)*68 + col] = make_float2(acc[j][2], acc[j][3]);
    }
    __syncthreads();
    {
        int c2 = (t & 31) * 2, grp = t >> 5;
        float b0 = sBm[c2], b1 = sBm[c2+1];
        float sc0 = sSc[c2], sc1 = sSc[c2+1];
        float sh0 = sSh[c2], sh1 = sSh[c2+1];
        float cs0 = 0.f, cs1 = 0.f, cq0 = 0.f, cq1 = 0.f;
#pragma unroll
        for (int i = 0; i < 16; i++) {
            int r = grp*16 + i;
            long p = tile0 + r;
            float2 m = *(float2*)&sO[r*68 + c2];
            float2 tv = *(const float2*)(Tprev + p*64 + c2);
            if (useNorm) {
                tv.x = fmaxf(fmaf(tv.x, sc0, sh0), 0.f);
                tv.y = fmaxf(fmaf(tv.y, sc1, sh1), 0.f);
            }
            float o0 = m.x + b0 + tv.x;
            float o1 = m.y + b1 + tv.y;
            *(float2*)(Tcur + p*64 + c2) = make_float2(o0, o1);
            cs0 += o0; cq0 += o0*o0;
            cs1 += o1; cq1 += o1*o1;
        }
        atomicAdd(&sSum[c2],   cs0);
        atomicAdd(&sSum[c2+1], cs1);
        atomicAdd(&sSq[c2],    cq0);
        atomicAdd(&sSq[c2+1],  cq1);
    }
    __syncthreads();
    if (t < 64) {
        atomicAdd(&oSum[b*64 + t], sSum[t]);
        atomicAdd(&oSq [b*64 + t], sSq[t]);
    }
}

// k_pool: normalized relu pooled sums; norm coefs computed inline per block.
__global__ void __launch_bounds__(256) k_pool(const float* __restrict__ T,
                                              const float* __restrict__ pSum,
                                              const float* __restrict__ pSq,
                                              const float* __restrict__ pGam,
                                              const float* __restrict__ pBet) {
    __shared__ float sp[64];
    __shared__ float sScP[64], sShP[64];
    int t = threadIdx.x;
    int b = blockIdx.x / 576;
    if (t < 64) {
        float sc, sh;
        norm_coef(pSum[b*64 + t], pSq[b*64 + t], pGam[t], pBet[t], sc, sh);
        sScP[t] = sc; sShP[t] = sh;
        sp[t] = 0.0f;
    }
    __syncthreads();
    long q = (long)blockIdx.x * 256 + t;
    long idx = q * 4;
    int d0 = (int)(idx & 63);
    float4 v  = *(const float4*)(T + idx);
    float4 sc = *(const float4*)&sScP[d0];
    float4 sh = *(const float4*)&sShP[d0];
    float4 o;
    o.x = fmaxf(fmaf(v.x, sc.x, sh.x), 0.0f);
    o.y = fmaxf(fmaf(v.y, sc.y, sh.y), 0.0f);
    o.z = fmaxf(fmaf(v.z, sc.z, sh.z), 0.0f);
    o.w = fmaxf(fmaf(v.w, sc.w, sh.w), 0.0f);
    atomicAdd(&sp[d0+0], o.x);
    atomicAdd(&sp[d0+1], o.y);
    atomicAdd(&sp[d0+2], o.z);
    atomicAdd(&sp[d0+3], o.w);
    __syncthreads();
    if (t < 64) atomicAdd(&g_pool[b*64 + t], sp[t]);
}

__global__ void k5_out(const float* __restrict__ pw,
                       const float* __restrict__ pb,
                       float* __restrict__ out) {
    int t = threadIdx.x;
    int b = t >> 5, lane = t & 31;
    float v = g_pool[b*64 + lane]      * pw[lane]
            + g_pool[b*64 + lane + 32] * pw[lane + 32];
#pragma unroll
    for (int o = 16; o > 0; o >>= 1) v += __shfl_down_sync(0xffffffffu, v, o);
    if (lane == 0) out[b] = v + pb[0];
}

// ---------------------------------------------------------------------------
extern "C" void kernel_launch(void* const* d_in, const int* in_sizes, int n_in,
                              void* d_out, int out_size) {
    (void)in_sizes; (void)n_in; (void)out_size;
    const int*   x    = (const int*)d_in[0];
    const int*   ei   = (const int*)d_in[1];
    const int*   ea   = (const int*)d_in[2];
    const float* nemb = (const float*)d_in[3];
    const float* eemb = (const float*)d_in[4];
    const float* W1   = (const float*)d_in[5];
    const float* b1   = (const float*)d_in[6];
    const float* W2   = (const float*)d_in[7];
    const float* b2   = (const float*)d_in[8];
    const float* Wm   = (const float*)d_in[9];
    const float* bm   = (const float*)d_in[10];
    const float* gam  = (const float*)d_in[11];
    const float* bet  = (const float*)d_in[12];
    const float* pw   = (const float*)d_in[13];
    const float* pb   = (const float*)d_in[14];
    float* out = (float*)d_out;

    float* gT0;  cudaGetSymbolAddress((void**)&gT0,  g_T0);
    float* gT1;  cudaGetSymbolAddress((void**)&gT1,  g_T1);
    float* gSum; cudaGetSymbolAddress((void**)&gSum, g_sumL);
    float* gSq;  cudaGetSymbolAddress((void**)&gSq,  g_sqL);
    void* pAux;  cudaGetSymbolAddress(&pAux,  g_aux);
    void* pDeg;  cudaGetSymbolAddress(&pDeg,  g_deg);
    void* pNp;   cudaGetSymbolAddress(&pNp,   g_npairs);
    void* pPool; cudaGetSymbolAddress(&pPool, g_pool);

    cudaFuncSetAttribute(k1_fused, cudaFuncAttributeMaxDynamicSharedMemorySize, SMEM_K1);
    cudaFuncSetAttribute(k3_mma,   cudaFuncAttributeMaxDynamicSharedMemorySize, SMEM_MMA);

    cudaMemsetAsync(pAux, 0xFF, PTOT * sizeof(int));          // g_aux = -1
    cudaMemsetAsync(pDeg, 0, BB*NN * sizeof(int));
    cudaMemsetAsync(pNp, 0, sizeof(int));
    cudaMemsetAsync(pPool, 0, BB*DD * sizeof(float));
    cudaMemsetAsync(gSum, 0, LL*BB*DD * sizeof(float));
    cudaMemsetAsync(gSq, 0, LL*BB*DD * sizeof(float));

    k_scatter<<<96, 256>>>(ei, ea);
    k_decode<<<1152, 256>>>();
    k_initW<<<18432, 256>>>(x, nemb, eemb);   // -> g_T1

    for (int l = 0; l < LL; l++) {
        float* Tprev = (l % 2 == 0) ? gT1 : gT0;
        float* Tcur  = (l % 2 == 0) ? gT0 : gT1;
        int useNorm  = (l > 0) ? 1 : 0;
        int lp = (l > 0) ? (l - 1) : 0;
        const float* pSum = gSum + lp*BB*DD;
        const float* pSq  = gSq  + lp*BB*DD;
        const float* pGam = gam + lp*64;
        const float* pBet = bet + lp*64;
        k1_fused<<<1920, 256, SMEM_K1>>>(Tprev, W1 + l*4096, b1 + l*64,
                                         W2 + l*4096, b2 + l*64, useNorm,
                                         pSum, pSq, pGam, pBet);
        k2_sparse<<<3072, 256>>>();
        k3_mma<<<2304, 256, SMEM_MMA>>>(Tprev, Wm + l*4096, bm + l*64,
                                        useNorm, Tcur,
                                        pSum, pSq, pGam, pBet,
                                        gSum + l*BB*DD, gSq + l*BB*DD);
    }
    k_pool<<<18432, 256>>>(gT0,
                           gSum + (LL-1)*BB*DD, gSq + (LL-1)*BB*DD,
                           gam + (LL-1)*64, bet + (LL-1)*64);
    k5_out<<<1, 1024>>>(pw, pb, out);
}